// round 15
// baseline (speedup 1.0000x reference)
#include <cuda_runtime.h>
#include <cstdint>

#define NB 64
#define NT 1024
#define NI 256
#define NH 512
#define NO 256

// ---------------- scratch (device globals: the sanctioned no-alloc path) ----------------
__device__ float g_xh[(size_t)NB * NT * NH];   // 128 MB: [t][b][h]
__device__ float g_hs[(size_t)NB * NT * NH];   // 128 MB: [b][t][h]
__device__ unsigned g_prog[16];                // per-cluster scan progress (chunks*8)
__device__ unsigned g_probe;                   // dummy target

// ---------------- helpers ----------------
__device__ __forceinline__ void fma2(unsigned long long& d, unsigned long long a,
                                     unsigned long long b) {
    asm("fma.rn.f32x2 %0, %1, %2, %0;" : "+l"(d) : "l"(a), "l"(b));
}
__device__ __forceinline__ unsigned long long pack2(float lo, float hi) {
    unsigned long long v;
    asm("mov.b64 %0, {%1, %2};" : "=l"(v) : "f"(lo), "f"(hi));
    return v;
}
__device__ __forceinline__ float f2sum(unsigned long long v) {
    float lo, hi;
    asm("mov.b64 {%0, %1}, %2;" : "=f"(lo), "=f"(hi) : "l"(v));
    return lo + hi;
}
__device__ __forceinline__ unsigned smem_u32(const void* p) {
    unsigned a;
    asm("{ .reg .u64 t; cvta.to.shared.u64 t, %1; cvt.u32.u64 %0, t; }"
        : "=r"(a) : "l"(p));
    return a;
}
__device__ __forceinline__ void mbar_init(unsigned a, unsigned cnt) {
    asm volatile("mbarrier.init.shared.b64 [%0], %1;" ::"r"(a), "r"(cnt) : "memory");
}
__device__ __forceinline__ void mbar_arrive_expect_tx(unsigned a, unsigned bytes) {
    asm volatile("mbarrier.arrive.expect_tx.shared.b64 _, [%0], %1;"
                 ::"r"(a), "r"(bytes) : "memory");
}
__device__ __forceinline__ void mbar_wait_parity(unsigned a, unsigned parity) {
    unsigned done;
    asm volatile(
        "{\n\t.reg .pred p;\n\t"
        "mbarrier.try_wait.parity.acquire.cta.shared::cta.b64 p, [%1], %2;\n\t"
        "selp.b32 %0, 1, 0, p;\n\t}"
        : "=r"(done) : "r"(a), "r"(parity) : "memory");
    if (!done) {
        asm volatile(
            "{\n\t.reg .pred P1;\n\t"
            "WAIT_LOOP_%=:\n\t"
            "mbarrier.try_wait.parity.acquire.cta.shared::cta.b64 P1, [%0], %1, 0x989680;\n\t"
            "@P1 bra.uni WAIT_DONE_%=;\n\t"
            "bra.uni WAIT_LOOP_%=;\n\t"
            "WAIT_DONE_%=:\n\t}"
            ::"r"(a), "r"(parity) : "memory");
    }
}
__device__ __forceinline__ void st_async_b64(unsigned addr, unsigned long long v,
                                             unsigned mbar) {
    asm volatile(
        "st.async.shared::cluster.mbarrier::complete_tx::bytes.b64 [%0], %1, [%2];"
        ::"r"(addr), "l"(v), "r"(mbar) : "memory");
}
__device__ __forceinline__ unsigned ld_acquire_u32(const unsigned* p) {
    unsigned v;
    asm volatile("ld.acquire.gpu.u32 %0, [%1];" : "=r"(v) : "l"(p) : "memory");
    return v;
}

// probe: zeroes the progress flags before each mega replay
__global__ void probe_kernel() {
    if (threadIdx.x < 16) g_prog[threadIdx.x] = 0u;
    if (threadIdx.x == 0) g_probe = 0u;
}

// =====================================================================================
// GEMM v4 (standalone, mode-0 only): xh = x @ W_xh + b_h. BM=128, BN=64, BK=32,
// cp.async double-buffered, 8x4 thread tile, f32x2. Writes g_xh [t][b][h].
// =====================================================================================
#define ASZ (128 * 36)
#define BSZ (64 * 36)

__global__ __launch_bounds__(256, 2) void gemm0_kernel(const float* __restrict__ A,
                                                       const float* __restrict__ Bm,
                                                       const float* __restrict__ bias) {
    extern __shared__ __align__(16) float gsm[];
    float* As = gsm;
    float* Bs = gsm + 2 * ASZ;

    const int tid = threadIdx.x;
    const int tn = tid & 15, tm = tid >> 4;
    const int n0 = blockIdx.x * 64;
    const int m0 = blockIdx.y * 128;
    const int N = NH;   // 512
    const int K = NI;   // 256

    const unsigned as_base = smem_u32(As);

    unsigned long long acc[8][4];
#pragma unroll
    for (int i = 0; i < 8; i++)
#pragma unroll
        for (int j = 0; j < 4; j++) acc[i][j] = 0ULL;

    const int a_m = tid >> 1, a_s = (tid & 1) * 16;
    const int b_k = tid >> 3, b_s = (tid & 7) * 8;

    auto issueA = [&](int k0, int b) {
        const float* ap = &A[(size_t)(m0 + a_m) * K + k0 + a_s];
        unsigned dst = as_base + (unsigned)(b * ASZ + a_m * 36 + a_s) * 4u;
#pragma unroll
        for (int ch = 0; ch < 4; ch++)
            asm volatile("cp.async.cg.shared.global [%0], [%1], 16;"
                         ::"r"(dst + ch * 16), "l"(ap + ch * 4) : "memory");
    };
    auto stsB = [&](int b, float4 v0, float4 v1) {
        float* B = Bs + b * BSZ;
        B[(b_s + 0) * 36 + b_k] = v0.x;
        B[(b_s + 1) * 36 + b_k] = v0.y;
        B[(b_s + 2) * 36 + b_k] = v0.z;
        B[(b_s + 3) * 36 + b_k] = v0.w;
        B[(b_s + 4) * 36 + b_k] = v1.x;
        B[(b_s + 5) * 36 + b_k] = v1.y;
        B[(b_s + 6) * 36 + b_k] = v1.z;
        B[(b_s + 7) * 36 + b_k] = v1.w;
    };

    {
        issueA(0, 0);
        asm volatile("cp.async.commit_group;" ::: "memory");
        const float* bp = &Bm[(size_t)b_k * N + n0 + b_s];
        float4 v0 = *(const float4*)bp;
        float4 v1 = *(const float4*)(bp + 4);
        asm volatile("cp.async.wait_group 0;" ::: "memory");
        stsB(0, v0, v1);
        __syncthreads();
    }

    int buf = 0;
    for (int k0 = 0; k0 < K; k0 += 32) {
        const int nxt = buf ^ 1;
        const bool more = (k0 + 32 < K);
        float4 nb0, nb1;
        if (more) {
            issueA(k0 + 32, nxt);
            asm volatile("cp.async.commit_group;" ::: "memory");
            const float* bp = &Bm[(size_t)(k0 + 32 + b_k) * N + n0 + b_s];
            nb0 = *(const float4*)bp;
            nb1 = *(const float4*)(bp + 4);
        }
        const float* Ab = As + buf * ASZ;
        const float* Bb = Bs + buf * BSZ;
#pragma unroll
        for (int kk = 0; kk < 32; kk += 4) {
            ulonglong2 bv[4];
#pragma unroll
            for (int j = 0; j < 4; j++)
                bv[j] = *(const ulonglong2*)&Bb[(tn + 16 * j) * 36 + kk];
#pragma unroll
            for (int i = 0; i < 8; i++) {
                ulonglong2 av = *(const ulonglong2*)&Ab[(tm + 16 * i) * 36 + kk];
#pragma unroll
                for (int j = 0; j < 4; j++) {
                    fma2(acc[i][j], av.x, bv[j].x);
                    fma2(acc[i][j], av.y, bv[j].y);
                }
            }
        }
        if (more) {
            asm volatile("cp.async.wait_group 0;" ::: "memory");
            stsB(nxt, nb0, nb1);
        }
        __syncthreads();
        buf = nxt;
    }

#pragma unroll
    for (int j = 0; j < 4; j++) {
        int n = n0 + tn + 16 * j;
        float bz = bias[n];
#pragma unroll
        for (int i = 0; i < 8; i++) {
            int m = m0 + tm + 16 * i;
            float v = f2sum(acc[i][j]) + bz;
            int b = m >> 10, t = m & 1023;
            g_xh[((size_t)t * NB + b) * NH + n] = v;
        }
    }
}

// =====================================================================================
// MEGA kernel: bids 0..127 = scan; bids 128..2175 = gemm<1> tiles gated on
// g_prog (t-chunk ordered). Scan v5: SELF-SEND — every slice, own included,
// travels via st.async.b64 and completes on the per-source mbar; warp w waits
// only on mbar w. ONE __syncthreads per step (red barrier). Ordering safety:
// red double-buffered (bar1/step separates t-reads from t+2-writes); hsm
// slice-p overwrite at t+2 is transitively gated behind my FMA(t+1) reads via
// peer p's wait on my t+1 sends; self-sends precede each warp's own wait in
// program order.
// =====================================================================================
__global__ __launch_bounds__(256) __cluster_dims__(8, 1, 1)
void mega_kernel(const float* __restrict__ W_hh, const float* __restrict__ W_hy,
                 const float* __restrict__ b_y, float* __restrict__ out) {
    extern __shared__ __align__(16) float smem[];

    const int tid = threadIdx.x;

    if (blockIdx.x < 128) {
        // ======================= SCAN branch =======================
        float* hsm = smem;                // [2][4][516]
        float* red = smem + 2 * 4 * 516;  // [2][16][4][64]
        __shared__ __align__(8) unsigned long long mbar[8];

        unsigned s;
        asm("mov.u32 %0, %%cluster_ctarank;" : "=r"(s));
        const int g = blockIdx.x >> 3;
        const int cc = tid & 15, ks = tid >> 4;
        const int rr = tid >> 6, c = tid & 63;
        const int w = tid >> 5;

        const unsigned mbar_base = smem_u32(mbar);
        const unsigned hsm_base = smem_u32(hsm);
        const int k0 = ks * 32;

        unsigned long long wreg[4][16];
#pragma unroll
        for (int cp = 0; cp < 4; cp++) {
            const float* wp = &W_hh[(size_t)k0 * NH + s * 64 + cc + 16 * cp];
#pragma unroll 4
            for (int j = 0; j < 16; j++) {
                float w0 = __ldg(wp + (size_t)(2 * j) * NH);
                float w1 = __ldg(wp + (size_t)(2 * j + 1) * NH);
                wreg[cp][j] = pack2(w0, w1);
            }
        }

        for (int idx = tid; idx < 2 * 4 * 516; idx += 256) hsm[idx] = 0.f;
        if (tid == 0) {
#pragma unroll
            for (int j = 0; j < 8; j++) {
                mbar_init(mbar_base + j * 8, 1);
                mbar_arrive_expect_tx(mbar_base + j * 8, 1024);
            }
        }
        __syncthreads();

        asm volatile("barrier.cluster.arrive.aligned;" ::: "memory");
        asm volatile("barrier.cluster.wait.aligned;" ::: "memory");

        unsigned remh[8], remb[8];
#pragma unroll
        for (int p = 0; p < 8; p++) {
            asm("mapa.shared::cluster.u32 %0, %1, %2;"
                : "=r"(remh[p]) : "r"(hsm_base), "r"((unsigned)p));
            asm("mapa.shared::cluster.u32 %0, %1, %2;"
                : "=r"(remb[p]) : "r"(mbar_base), "r"((unsigned)p));
        }

        const unsigned my_elem = (unsigned)(rr * 516 + s * 64 + c) * 4u;
        const bool sender = ((c & 1) == 0);
        const unsigned mbar_src_off = s * 8u;
        const float* xp = &g_xh[(size_t)(g * 4 + rr) * NH + s * 64 + c];

        float xval = __ldg(xp);

        for (int t = 0; t < NT; t++) {
            float xnext =
                (t + 1 < NT) ? __ldg(xp + (size_t)(t + 1) * (NB * NH)) : 0.f;

            const float* hcur = hsm + (t & 1) * (4 * 516);
            float* redt = red + (t & 1) * (16 * 4 * 64);

            unsigned long long acc[4][4];
#pragma unroll
            for (int r = 0; r < 4; r++)
#pragma unroll
                for (int cp = 0; cp < 4; cp++) acc[r][cp] = 0ULL;

#pragma unroll
            for (int kk = 0; kk < 32; kk += 4) {
                ulonglong2 hv[4];
#pragma unroll
                for (int r = 0; r < 4; r++)
                    hv[r] = *(const ulonglong2*)&hcur[r * 516 + k0 + kk];
#pragma unroll
                for (int cp = 0; cp < 4; cp++) {
#pragma unroll
                    for (int r = 0; r < 4; r++) {
                        fma2(acc[r][cp], wreg[cp][kk / 2], hv[r].x);
                        fma2(acc[r][cp], wreg[cp][kk / 2 + 1], hv[r].y);
                    }
                }
            }
#pragma unroll
            for (int r = 0; r < 4; r++)
#pragma unroll
                for (int cp = 0; cp < 4; cp++)
                    redt[(ks * 4 + r) * 64 + cc + 16 * cp] = f2sum(acc[r][cp]);
            __syncthreads();  // the ONE barrier per step

            float v = xval;
#pragma unroll
            for (int q = 0; q < 16; q++) v += redt[(q * 4 + rr) * 64 + c];
            float h = tanhf(v);

            if (t + 1 < NT) {
                const unsigned nb = (t + 1) & 1;
                const unsigned boff = nb * (4 * 516 * 4) + my_elem;

                float hn = __shfl_down_sync(0xffffffffu, h, 1);
                if (sender) {
                    unsigned long long pair = pack2(h, hn);
#pragma unroll
                    for (int p = 0; p < 8; p++)  // self included
                        st_async_b64(remh[p] + boff, pair,
                                     remb[p] + mbar_src_off);
                }
            }

            g_hs[((size_t)(g * 4 + rr) * NT + t) * NH + s * 64 + c] = h;

            // progress publish: chunk (t>>7) complete for this CTA's slice
            if ((t & 127) == 127) {
                __threadfence();
                __syncthreads();
                if (tid == 0) atomicAdd(&g_prog[g], 1u);
            }

            if (t + 1 < NT) {
                // every warp (own slice included) waits on its source mbar
                if ((tid & 31) == 0) {
                    mbar_wait_parity(mbar_base + w * 8u, (unsigned)(t & 1));
                    mbar_arrive_expect_tx(mbar_base + w * 8u, 1024);
                }
                __syncwarp();
            }
            xval = xnext;
        }

        asm volatile("barrier.cluster.arrive.aligned;" ::: "memory");
        asm volatile("barrier.cluster.wait.aligned;" ::: "memory");
        return;
    }

    // ======================= GEMM<1> branch =======================
    const int tile = blockIdx.x - 128;   // 0..2047
    const int tc = tile >> 8;            // t-chunk 0..7
    const int within = tile & 255;       // 0..255
    const int b = within >> 2;           // batch 0..63
    const int nblk = within & 3;         // n-block 0..3

    if (tid == 0) {
        const unsigned need = 8u * (unsigned)(tc + 1);
        while (ld_acquire_u32(&g_prog[b >> 2]) < need) {
        }
    }
    __syncthreads();

    float* As = smem;
    float* Bs = smem + 2 * ASZ;

    const int tn = tid & 15, tm = tid >> 4;
    const int n0 = nblk * 64;
    const int m0 = b * 1024 + tc * 128;
    const int N = NO;   // 256
    const int K = NH;   // 512

    const float* Ap = (const float*)g_hs;
    const unsigned as_base = smem_u32(As);

    unsigned long long acc[8][4];
#pragma unroll
    for (int i = 0; i < 8; i++)
#pragma unroll
        for (int j = 0; j < 4; j++) acc[i][j] = 0ULL;

    const int a_m = tid >> 1, a_s = (tid & 1) * 16;
    const int b_k = tid >> 3, b_s = (tid & 7) * 8;

    auto issueA = [&](int k0, int bb) {
        const float* ap = &Ap[(size_t)(m0 + a_m) * K + k0 + a_s];
        unsigned dst = as_base + (unsigned)(bb * ASZ + a_m * 36 + a_s) * 4u;
#pragma unroll
        for (int ch = 0; ch < 4; ch++)
            asm volatile("cp.async.cg.shared.global [%0], [%1], 16;"
                         ::"r"(dst + ch * 16), "l"(ap + ch * 4) : "memory");
    };
    auto stsB = [&](int bb, float4 v0, float4 v1) {
        float* B = Bs + bb * BSZ;
        B[(b_s + 0) * 36 + b_k] = v0.x;
        B[(b_s + 1) * 36 + b_k] = v0.y;
        B[(b_s + 2) * 36 + b_k] = v0.z;
        B[(b_s + 3) * 36 + b_k] = v0.w;
        B[(b_s + 4) * 36 + b_k] = v1.x;
        B[(b_s + 5) * 36 + b_k] = v1.y;
        B[(b_s + 6) * 36 + b_k] = v1.z;
        B[(b_s + 7) * 36 + b_k] = v1.w;
    };

    {
        issueA(0, 0);
        asm volatile("cp.async.commit_group;" ::: "memory");
        const float* bp = &W_hy[(size_t)b_k * N + n0 + b_s];
        float4 v0 = *(const float4*)bp;
        float4 v1 = *(const float4*)(bp + 4);
        asm volatile("cp.async.wait_group 0;" ::: "memory");
        stsB(0, v0, v1);
        __syncthreads();
    }

    int buf = 0;
    for (int k0 = 0; k0 < K; k0 += 32) {
        const int nxt = buf ^ 1;
        const bool more = (k0 + 32 < K);
        float4 nb0, nb1;
        if (more) {
            issueA(k0 + 32, nxt);
            asm volatile("cp.async.commit_group;" ::: "memory");
            const float* bp = &W_hy[(size_t)(k0 + 32 + b_k) * N + n0 + b_s];
            nb0 = *(const float4*)bp;
            nb1 = *(const float4*)(bp + 4);
        }
        const float* Ab = As + buf * ASZ;
        const float* Bb = Bs + buf * BSZ;
#pragma unroll
        for (int kk = 0; kk < 32; kk += 4) {
            ulonglong2 bv[4];
#pragma unroll
            for (int j = 0; j < 4; j++)
                bv[j] = *(const ulonglong2*)&Bb[(tn + 16 * j) * 36 + kk];
#pragma unroll
            for (int i = 0; i < 8; i++) {
                ulonglong2 av = *(const ulonglong2*)&Ab[(tm + 16 * i) * 36 + kk];
#pragma unroll
                for (int j = 0; j < 4; j++) {
                    fma2(acc[i][j], av.x, bv[j].x);
                    fma2(acc[i][j], av.y, bv[j].y);
                }
            }
        }
        if (more) {
            asm volatile("cp.async.wait_group 0;" ::: "memory");
            stsB(nxt, nb0, nb1);
        }
        __syncthreads();
        buf = nxt;
    }

#pragma unroll
    for (int j = 0; j < 4; j++) {
        int n = n0 + tn + 16 * j;
        float bz = b_y[n];
#pragma unroll
        for (int i = 0; i < 8; i++) {
            int m = m0 + tm + 16 * i;
            out[(size_t)m * NO + n] = f2sum(acc[i][j]) + bz;
        }
    }
}

// =====================================================================================
extern "C" void kernel_launch(void* const* d_in, const int* in_sizes, int n_in,
                              void* d_out, int out_size) {
    const float* x = (const float*)d_in[0];
    const float* W_xh = (const float*)d_in[1];
    const float* W_hh = (const float*)d_in[2];
    const float* b_h = (const float*)d_in[3];
    const float* W_hy = (const float*)d_in[4];
    const float* b_y = (const float*)d_in[5];
    float* out = (float*)d_out;

    const int gemm_smem = (2 * ASZ + 2 * BSZ) * (int)sizeof(float);  // 55.3 KB
    cudaFuncSetAttribute(gemm0_kernel, cudaFuncAttributeMaxDynamicSharedMemorySize,
                         gemm_smem);
    cudaFuncSetAttribute(mega_kernel, cudaFuncAttributeMaxDynamicSharedMemorySize,
                         gemm_smem);

    probe_kernel<<<1, 32>>>();                                   // zero g_prog
    gemm0_kernel<<<dim3(8, 512), 256, gemm_smem>>>(x, W_xh, b_h);
    probe_kernel<<<1, 32>>>();
    mega_kernel<<<128 + 2048, 256, gemm_smem>>>(W_hh, W_hy, b_y, out);
}

// round 16
// speedup vs baseline: 1.0323x; 1.0323x over previous
#include <cuda_runtime.h>
#include <cstdint>

#define NB 64
#define NT 1024
#define NI 256
#define NH 512
#define NO 256

// ---------------- scratch (device globals: the sanctioned no-alloc path) ----------------
__device__ float g_xh[(size_t)NB * NT * NH];   // 128 MB: [t][b][h]
__device__ float g_hs[(size_t)NB * NT * NH];   // 128 MB: [b][t][h]
__device__ unsigned g_prog[16];                // per-cluster scan progress (chunks*8)
__device__ unsigned g_probe;                   // dummy target

// ---------------- helpers ----------------
__device__ __forceinline__ void fma2(unsigned long long& d, unsigned long long a,
                                     unsigned long long b) {
    asm("fma.rn.f32x2 %0, %1, %2, %0;" : "+l"(d) : "l"(a), "l"(b));
}
__device__ __forceinline__ unsigned long long pack2(float lo, float hi) {
    unsigned long long v;
    asm("mov.b64 %0, {%1, %2};" : "=l"(v) : "f"(lo), "f"(hi));
    return v;
}
__device__ __forceinline__ float f2sum(unsigned long long v) {
    float lo, hi;
    asm("mov.b64 {%0, %1}, %2;" : "=f"(lo), "=f"(hi) : "l"(v));
    return lo + hi;
}
__device__ __forceinline__ unsigned smem_u32(const void* p) {
    unsigned a;
    asm("{ .reg .u64 t; cvta.to.shared.u64 t, %1; cvt.u32.u64 %0, t; }"
        : "=r"(a) : "l"(p));
    return a;
}
__device__ __forceinline__ void mbar_init(unsigned a, unsigned cnt) {
    asm volatile("mbarrier.init.shared.b64 [%0], %1;" ::"r"(a), "r"(cnt) : "memory");
}
__device__ __forceinline__ void mbar_arrive_expect_tx(unsigned a, unsigned bytes) {
    asm volatile("mbarrier.arrive.expect_tx.shared.b64 _, [%0], %1;"
                 ::"r"(a), "r"(bytes) : "memory");
}
__device__ __forceinline__ void mbar_wait_parity(unsigned a, unsigned parity) {
    unsigned done;
    asm volatile(
        "{\n\t.reg .pred p;\n\t"
        "mbarrier.try_wait.parity.acquire.cta.shared::cta.b64 p, [%1], %2;\n\t"
        "selp.b32 %0, 1, 0, p;\n\t}"
        : "=r"(done) : "r"(a), "r"(parity) : "memory");
    if (!done) {
        asm volatile(
            "{\n\t.reg .pred P1;\n\t"
            "WAIT_LOOP_%=:\n\t"
            "mbarrier.try_wait.parity.acquire.cta.shared::cta.b64 P1, [%0], %1, 0x989680;\n\t"
            "@P1 bra.uni WAIT_DONE_%=;\n\t"
            "bra.uni WAIT_LOOP_%=;\n\t"
            "WAIT_DONE_%=:\n\t}"
            ::"r"(a), "r"(parity) : "memory");
    }
}
__device__ __forceinline__ void st_async_b64(unsigned addr, unsigned long long v,
                                             unsigned mbar) {
    asm volatile(
        "st.async.shared::cluster.mbarrier::complete_tx::bytes.b64 [%0], %1, [%2];"
        ::"r"(addr), "l"(v), "r"(mbar) : "memory");
}
__device__ __forceinline__ unsigned ld_acquire_u32(const unsigned* p) {
    unsigned v;
    asm volatile("ld.acquire.gpu.u32 %0, [%1];" : "=r"(v) : "l"(p) : "memory");
    return v;
}

// probe: zeroes the progress flags before each mega replay
__global__ void probe_kernel() {
    if (threadIdx.x < 16) g_prog[threadIdx.x] = 0u;
    if (threadIdx.x == 0) g_probe = 0u;
}

// =====================================================================================
// GEMM0 v5: xh = x @ W_xh + b_h. BM=128, BN=64, BK=32, 8x4 thread tile, f32x2.
// THREE-stage A pipeline (cp.async, buffers i, i+1, i+2) + 2-ahead B register
// prefetch: compute(i) runs with A(i+1) resident, A(i+2)+B(i+2) in flight.
// wait_group 1 before stsB(i+1) -> A-latency fully hidden. 73.7 KB smem, 2 CTAs/SM.
// =====================================================================================
#define ASZ (128 * 36)
#define BSZ (64 * 36)

__global__ __launch_bounds__(256, 2) void gemm0_kernel(const float* __restrict__ A,
                                                       const float* __restrict__ Bm,
                                                       const float* __restrict__ bias) {
    extern __shared__ __align__(16) float gsm[];
    float* As = gsm;            // [3][128][36]
    float* Bs = gsm + 3 * ASZ;  // [2][64][36] ([n][k] transposed)

    const int tid = threadIdx.x;
    const int tn = tid & 15, tm = tid >> 4;
    const int n0 = blockIdx.x * 64;
    const int m0 = blockIdx.y * 128;
    const int N = NH;   // 512
    const int K = NI;   // 256
    const int T = K / 32;  // 8 k-tiles

    const unsigned as_base = smem_u32(As);

    unsigned long long acc[8][4];
#pragma unroll
    for (int i = 0; i < 8; i++)
#pragma unroll
        for (int j = 0; j < 4; j++) acc[i][j] = 0ULL;

    const int a_m = tid >> 1, a_s = (tid & 1) * 16;
    const int b_k = tid >> 3, b_s = (tid & 7) * 8;

    auto issueA = [&](int ti, int b) {
        const float* ap = &A[(size_t)(m0 + a_m) * K + ti * 32 + a_s];
        unsigned dst = as_base + (unsigned)(b * ASZ + a_m * 36 + a_s) * 4u;
#pragma unroll
        for (int ch = 0; ch < 4; ch++)
            asm volatile("cp.async.cg.shared.global [%0], [%1], 16;"
                         ::"r"(dst + ch * 16), "l"(ap + ch * 4) : "memory");
        asm volatile("cp.async.commit_group;" ::: "memory");
    };
    auto ldgB = [&](int ti, float4& v0, float4& v1) {
        const float* bp = &Bm[(size_t)(ti * 32 + b_k) * N + n0 + b_s];
        v0 = *(const float4*)bp;
        v1 = *(const float4*)(bp + 4);
    };
    auto stsB = [&](int b, float4 v0, float4 v1) {
        float* B = Bs + b * BSZ;
        B[(b_s + 0) * 36 + b_k] = v0.x;
        B[(b_s + 1) * 36 + b_k] = v0.y;
        B[(b_s + 2) * 36 + b_k] = v0.z;
        B[(b_s + 3) * 36 + b_k] = v0.w;
        B[(b_s + 4) * 36 + b_k] = v1.x;
        B[(b_s + 5) * 36 + b_k] = v1.y;
        B[(b_s + 6) * 36 + b_k] = v1.z;
        B[(b_s + 7) * 36 + b_k] = v1.w;
    };

    // prologue: A(0), A(1) in flight; B(0) staged; B(1) in regs
    float4 c0, c1, x0, x1;
    issueA(0, 0);
    issueA(1, 1);
    ldgB(0, c0, c1);
    stsB(0, c0, c1);
    ldgB(1, c0, c1);                              // cur = B(1)
    asm volatile("cp.async.wait_group 1;" ::: "memory");  // A(0) ready
    __syncthreads();

    for (int i = 0; i < T; i++) {
        if (i + 2 < T) {
            issueA(i + 2, (i + 2) % 3);
            ldgB(i + 2, x0, x1);                  // next = B(i+2)
        }

        const float* Ab = As + (i % 3) * ASZ;
        const float* Bb = Bs + (i & 1) * BSZ;
#pragma unroll
        for (int kk = 0; kk < 32; kk += 4) {
            ulonglong2 bv[4];
#pragma unroll
            for (int j = 0; j < 4; j++)
                bv[j] = *(const ulonglong2*)&Bb[(tn + 16 * j) * 36 + kk];
#pragma unroll
            for (int ii = 0; ii < 8; ii++) {
                ulonglong2 av = *(const ulonglong2*)&Ab[(tm + 16 * ii) * 36 + kk];
#pragma unroll
                for (int j = 0; j < 4; j++) {
                    fma2(acc[ii][j], av.x, bv[j].x);
                    fma2(acc[ii][j], av.y, bv[j].y);
                }
            }
        }

        if (i + 1 < T) {
            // ensure A(i+1) landed (leave A(i+2) outstanding), stage B(i+1)
            if (i + 2 < T)
                asm volatile("cp.async.wait_group 1;" ::: "memory");
            else
                asm volatile("cp.async.wait_group 0;" ::: "memory");
            stsB((i + 1) & 1, c0, c1);
            c0 = x0;
            c1 = x1;
        }
        __syncthreads();
    }

#pragma unroll
    for (int j = 0; j < 4; j++) {
        int n = n0 + tn + 16 * j;
        float bz = bias[n];
#pragma unroll
        for (int i = 0; i < 8; i++) {
            int m = m0 + tm + 16 * i;
            float v = f2sum(acc[i][j]) + bz;
            int b = m >> 10, t = m & 1023;
            g_xh[((size_t)t * NB + b) * NH + n] = v;
        }
    }
}

// =====================================================================================
// MEGA kernel (R12-proven, 2839 us): bids 0..127 = scan (R7 core + progress
// publish every 128 steps); bids 128..2175 = gemm<1> tiles, t-chunk ordered,
// gated on g_prog.
// =====================================================================================
__global__ __launch_bounds__(256) __cluster_dims__(8, 1, 1)
void mega_kernel(const float* __restrict__ W_hh, const float* __restrict__ W_hy,
                 const float* __restrict__ b_y, float* __restrict__ out) {
    extern __shared__ __align__(16) float smem[];

    const int tid = threadIdx.x;

    if (blockIdx.x < 128) {
        // ======================= SCAN branch (R12/R7 core) =======================
        float* hsm = smem;                // [2][4][516]
        float* red = smem + 2 * 4 * 516;  // [2][16][4][64]
        __shared__ __align__(8) unsigned long long mbar[8];

        unsigned s;
        asm("mov.u32 %0, %%cluster_ctarank;" : "=r"(s));
        const int g = blockIdx.x >> 3;
        const int cc = tid & 15, ks = tid >> 4;
        const int rr = tid >> 6, c = tid & 63;
        const int w = tid >> 5;

        const unsigned mbar_base = smem_u32(mbar);
        const unsigned hsm_base = smem_u32(hsm);
        const int k0 = ks * 32;

        unsigned long long wreg[4][16];
#pragma unroll
        for (int cp = 0; cp < 4; cp++) {
            const float* wp = &W_hh[(size_t)k0 * NH + s * 64 + cc + 16 * cp];
#pragma unroll 4
            for (int j = 0; j < 16; j++) {
                float w0 = __ldg(wp + (size_t)(2 * j) * NH);
                float w1 = __ldg(wp + (size_t)(2 * j + 1) * NH);
                wreg[cp][j] = pack2(w0, w1);
            }
        }

        for (int idx = tid; idx < 2 * 4 * 516; idx += 256) hsm[idx] = 0.f;
        if (tid == 0) {
#pragma unroll
            for (int j = 0; j < 8; j++) {
                mbar_init(mbar_base + j * 8, 1);
                mbar_arrive_expect_tx(mbar_base + j * 8, 1024);
            }
        }
        __syncthreads();

        asm volatile("barrier.cluster.arrive.aligned;" ::: "memory");
        asm volatile("barrier.cluster.wait.aligned;" ::: "memory");

        unsigned remh[8], remb[8];
#pragma unroll
        for (int p = 0; p < 8; p++) {
            asm("mapa.shared::cluster.u32 %0, %1, %2;"
                : "=r"(remh[p]) : "r"(hsm_base), "r"((unsigned)p));
            asm("mapa.shared::cluster.u32 %0, %1, %2;"
                : "=r"(remb[p]) : "r"(mbar_base), "r"((unsigned)p));
        }

        const unsigned my_elem = (unsigned)(rr * 516 + s * 64 + c) * 4u;
        const bool sender = ((c & 1) == 0);
        const unsigned mbar_src_off = s * 8u;
        const float* xp = &g_xh[(size_t)(g * 4 + rr) * NH + s * 64 + c];

        float xval = __ldg(xp);

        for (int t = 0; t < NT; t++) {
            float xnext =
                (t + 1 < NT) ? __ldg(xp + (size_t)(t + 1) * (NB * NH)) : 0.f;

            const float* hcur = hsm + (t & 1) * (4 * 516);
            float* redt = red + (t & 1) * (16 * 4 * 64);

            unsigned long long acc[4][4];
#pragma unroll
            for (int r = 0; r < 4; r++)
#pragma unroll
                for (int cp = 0; cp < 4; cp++) acc[r][cp] = 0ULL;

#pragma unroll
            for (int kk = 0; kk < 32; kk += 4) {
                ulonglong2 hv[4];
#pragma unroll
                for (int r = 0; r < 4; r++)
                    hv[r] = *(const ulonglong2*)&hcur[r * 516 + k0 + kk];
#pragma unroll
                for (int cp = 0; cp < 4; cp++) {
#pragma unroll
                    for (int r = 0; r < 4; r++) {
                        fma2(acc[r][cp], wreg[cp][kk / 2], hv[r].x);
                        fma2(acc[r][cp], wreg[cp][kk / 2 + 1], hv[r].y);
                    }
                }
            }
#pragma unroll
            for (int r = 0; r < 4; r++)
#pragma unroll
                for (int cp = 0; cp < 4; cp++)
                    redt[(ks * 4 + r) * 64 + cc + 16 * cp] = f2sum(acc[r][cp]);
            __syncthreads();

            float v = xval;
#pragma unroll
            for (int q = 0; q < 16; q++) v += redt[(q * 4 + rr) * 64 + c];
            float h = tanhf(v);

            if (t + 1 < NT) {
                const unsigned nb = (t + 1) & 1;
                const unsigned boff = nb * (4 * 516 * 4) + my_elem;

                float hn = __shfl_down_sync(0xffffffffu, h, 1);
                hsm[nb * (4 * 516) + rr * 516 + s * 64 + c] = h;

                if (sender) {
                    unsigned long long pair = pack2(h, hn);
#pragma unroll
                    for (int p = 0; p < 8; p++) {
                        if (p != (int)s)
                            st_async_b64(remh[p] + boff, pair,
                                         remb[p] + mbar_src_off);
                    }
                }
            }

            g_hs[((size_t)(g * 4 + rr) * NT + t) * NH + s * 64 + c] = h;

            // progress publish: chunk (t>>7) complete for this CTA's slice
            if ((t & 127) == 127) {
                __threadfence();
                __syncthreads();
                if (tid == 0) atomicAdd(&g_prog[g], 1u);
            }

            if (t + 1 < NT) {
                __syncthreads();
                if (w != (int)s) {
                    if ((tid & 31) == 0) {
                        mbar_wait_parity(mbar_base + w * 8u, (unsigned)(t & 1));
                        mbar_arrive_expect_tx(mbar_base + w * 8u, 1024);
                    }
                    __syncwarp();
                }
            }
            xval = xnext;
        }

        asm volatile("barrier.cluster.arrive.aligned;" ::: "memory");
        asm volatile("barrier.cluster.wait.aligned;" ::: "memory");
        return;
    }

    // ======================= GEMM<1> branch =======================
    const int tile = blockIdx.x - 128;   // 0..2047
    const int tc = tile >> 8;            // t-chunk 0..7
    const int within = tile & 255;       // 0..255
    const int b = within >> 2;           // batch 0..63
    const int nblk = within & 3;         // n-block 0..3

    if (tid == 0) {
        const unsigned need = 8u * (unsigned)(tc + 1);
        while (ld_acquire_u32(&g_prog[b >> 2]) < need) {
        }
    }
    __syncthreads();

    float* As = smem;
    float* Bs = smem + 2 * ASZ;

    const int tn = tid & 15, tm = tid >> 4;
    const int n0 = nblk * 64;
    const int m0 = b * 1024 + tc * 128;
    const int N = NO;   // 256
    const int K = NH;   // 512

    const float* Ap = (const float*)g_hs;
    const unsigned as_base = smem_u32(As);

    unsigned long long acc[8][4];
#pragma unroll
    for (int i = 0; i < 8; i++)
#pragma unroll
        for (int j = 0; j < 4; j++) acc[i][j] = 0ULL;

    const int a_m = tid >> 1, a_s = (tid & 1) * 16;
    const int b_k = tid >> 3, b_s = (tid & 7) * 8;

    auto issueA = [&](int k0, int bb) {
        const float* ap = &Ap[(size_t)(m0 + a_m) * K + k0 + a_s];
        unsigned dst = as_base + (unsigned)(bb * ASZ + a_m * 36 + a_s) * 4u;
#pragma unroll
        for (int ch = 0; ch < 4; ch++)
            asm volatile("cp.async.cg.shared.global [%0], [%1], 16;"
                         ::"r"(dst + ch * 16), "l"(ap + ch * 4) : "memory");
    };
    auto stsB = [&](int bb, float4 v0, float4 v1) {
        float* B = Bs + bb * BSZ;
        B[(b_s + 0) * 36 + b_k] = v0.x;
        B[(b_s + 1) * 36 + b_k] = v0.y;
        B[(b_s + 2) * 36 + b_k] = v0.z;
        B[(b_s + 3) * 36 + b_k] = v0.w;
        B[(b_s + 4) * 36 + b_k] = v1.x;
        B[(b_s + 5) * 36 + b_k] = v1.y;
        B[(b_s + 6) * 36 + b_k] = v1.z;
        B[(b_s + 7) * 36 + b_k] = v1.w;
    };

    {
        issueA(0, 0);
        asm volatile("cp.async.commit_group;" ::: "memory");
        const float* bp = &W_hy[(size_t)b_k * N + n0 + b_s];
        float4 v0 = *(const float4*)bp;
        float4 v1 = *(const float4*)(bp + 4);
        asm volatile("cp.async.wait_group 0;" ::: "memory");
        stsB(0, v0, v1);
        __syncthreads();
    }

    int buf = 0;
    for (int k0 = 0; k0 < K; k0 += 32) {
        const int nxt = buf ^ 1;
        const bool more = (k0 + 32 < K);
        float4 nb0, nb1;
        if (more) {
            issueA(k0 + 32, nxt);
            asm volatile("cp.async.commit_group;" ::: "memory");
            const float* bp = &W_hy[(size_t)(k0 + 32 + b_k) * N + n0 + b_s];
            nb0 = *(const float4*)bp;
            nb1 = *(const float4*)(bp + 4);
        }
        const float* Ab = As + buf * ASZ;
        const float* Bb = Bs + buf * BSZ;
#pragma unroll
        for (int kk = 0; kk < 32; kk += 4) {
            ulonglong2 bv[4];
#pragma unroll
            for (int j = 0; j < 4; j++)
                bv[j] = *(const ulonglong2*)&Bb[(tn + 16 * j) * 36 + kk];
#pragma unroll
            for (int i = 0; i < 8; i++) {
                ulonglong2 av = *(const ulonglong2*)&Ab[(tm + 16 * i) * 36 + kk];
#pragma unroll
                for (int j = 0; j < 4; j++) {
                    fma2(acc[i][j], av.x, bv[j].x);
                    fma2(acc[i][j], av.y, bv[j].y);
                }
            }
        }
        if (more) {
            asm volatile("cp.async.wait_group 0;" ::: "memory");
            stsB(nxt, nb0, nb1);
        }
        __syncthreads();
        buf = nxt;
    }

#pragma unroll
    for (int j = 0; j < 4; j++) {
        int n = n0 + tn + 16 * j;
        float bz = b_y[n];
#pragma unroll
        for (int i = 0; i < 8; i++) {
            int m = m0 + tm + 16 * i;
            out[(size_t)m * NO + n] = f2sum(acc[i][j]) + bz;
        }
    }
}

// =====================================================================================
extern "C" void kernel_launch(void* const* d_in, const int* in_sizes, int n_in,
                              void* d_out, int out_size) {
    const float* x = (const float*)d_in[0];
    const float* W_xh = (const float*)d_in[1];
    const float* W_hh = (const float*)d_in[2];
    const float* b_h = (const float*)d_in[3];
    const float* W_hy = (const float*)d_in[4];
    const float* b_y = (const float*)d_in[5];
    float* out = (float*)d_out;

    const int g0_smem = (3 * ASZ + 2 * BSZ) * (int)sizeof(float);    // 73.7 KB
    const int mega_smem = (2 * ASZ + 2 * BSZ) * (int)sizeof(float);  // 55.3 KB
    cudaFuncSetAttribute(gemm0_kernel, cudaFuncAttributeMaxDynamicSharedMemorySize,
                         g0_smem);
    cudaFuncSetAttribute(mega_kernel, cudaFuncAttributeMaxDynamicSharedMemorySize,
                         mega_smem);

    probe_kernel<<<1, 32>>>();                                   // zero g_prog
    gemm0_kernel<<<dim3(8, 512), 256, g0_smem>>>(x, W_xh, b_h);
    probe_kernel<<<1, 32>>>();
    mega_kernel<<<128 + 2048, 256, mega_smem>>>(W_hh, W_hy, b_y, out);
}